// round 7
// baseline (speedup 1.0000x reference)
#include <cuda_runtime.h>
#include <cuda_bf16.h>
#include <stdint.h>

#define N_NODES  100000
#define N_EDGES  3200000
#define N_FEAT   128
#define HIDDEN   64
#define N_GRAPHS 256

// Padded CSC capacity: E + 3 per node + 8 slack for unroll-8 overread
#define CSC_CAP  (N_EDGES + 4 * N_NODES + 8)
#define NCHUNK   ((N_NODES + 255) / 256)     // 391 chunks of 256 nodes

// ---------------- device scratch ----------------
__device__ __align__(16) static __nv_bfloat162 g_P [N_NODES * 32];  // layer-1 messages
__device__ __align__(16) static __nv_bfloat162 g_P2[N_NODES * 32];  // layer-2 messages (separate: L1 staleness)
__device__ __align__(16) static __nv_bfloat162 g_H1[N_NODES * 32];  // layer-1 out
__device__ __align__(16) static __nv_bfloat162 g_H2[N_NODES * 32];  // layer-2 out
__device__ __align__(16) static int   g_csc[CSC_CAP];               // pad slots stay 0
__device__              static int   g_deg[N_NODES];
__device__              static int   g_rowptr[N_NODES];
__device__              static int   g_cursor[N_NODES];
__device__              static float g_dinv[N_NODES];
__device__              static int   g_csum[NCHUNK];

// ---------------- epoch grid barrier (all resident blocks) ----------------
__device__          static unsigned          g_cnt;     // zero-init
__device__ volatile static unsigned          g_epoch;   // zero-init

__device__ __forceinline__ void gbar() {
    __threadfence();                    // make this block's writes visible device-wide
    __syncthreads();
    if (threadIdx.x == 0) {
        unsigned my = g_epoch;
        if (atomicAdd(&g_cnt, 1u) == gridDim.x - 1u) {
            g_cnt = 0;
            __threadfence();
            g_epoch = my + 1u;          // release
        } else {
            while (g_epoch == my) __nanosleep(64);
        }
        __threadfence();
    }
    __syncthreads();
}

// ---------------- f32x2 helpers ----------------
__device__ __forceinline__ unsigned long long dup_f32(float x) {
    unsigned long long r;
    unsigned xb = __float_as_uint(x);
    asm("mov.b64 %0, {%1, %1};" : "=l"(r) : "r"(xb));
    return r;
}
__device__ __forceinline__ void fma2(unsigned long long& acc, unsigned long long a,
                                     unsigned long long b) {
    asm("fma.rn.f32x2 %0, %1, %2, %0;" : "+l"(acc) : "l"(a), "l"(b));
}
__device__ __forceinline__ void unpack2(unsigned long long v, float& lo, float& hi) {
    asm("mov.b64 {%0, %1}, %2;" : "=f"(lo), "=f"(hi) : "l"(v));
}

__device__ __forceinline__ void emit_row(__nv_bfloat162* __restrict__ P,
                                         int row, int lane, float c0, float c1) {
    if (row < N_NODES) {
        float s = g_dinv[row];
        P[row * 32 + lane] = __floats2bfloat162_rn(c0 * s, c1 * s);
    }
}

// ---------------- GEMM1 phase: P = (X[fp32,K=128] @ W1) * dinv, bf16 out ----------
__device__ void phase_gemm1(const float* __restrict__ X, const float* __restrict__ W,
                            unsigned char* dyn, int idx, int nb) {
    float2*     sW = (float2*)dyn;                 // 32KB
    ulonglong2* sx = (ulonglong2*)(dyn + 32768);   // 32KB
    const float2* W2 = (const float2*)W;
    for (int t = threadIdx.x; t < 128 * 32; t += 256) sW[t] = W2[t];
    __syncthreads();

    int warp = threadIdx.x >> 5, lane = threadIdx.x & 31;
    ulonglong2* sxA = sx + warp * 256;
    ulonglong2* sxB = sxA + 128;
    const int NG = (N_NODES + 63) >> 6;

    for (int g = idx; g < NG; g += nb) {
        int row0 = g * 64 + warp * 8;
        #pragma unroll
        for (int j = 0; j < 4; j++) {
            int k = lane + 32 * j;
            float v[8];
            #pragma unroll
            for (int r = 0; r < 8; r++) {
                int rr = row0 + r; if (rr >= N_NODES) rr = N_NODES - 1;
                v[r] = X[(size_t)rr * 128 + k];
            }
            float4 fa = make_float4(v[0], v[1], v[2], v[3]);
            float4 fb = make_float4(v[4], v[5], v[6], v[7]);
            sxA[k] = *reinterpret_cast<ulonglong2*>(&fa);
            sxB[k] = *reinterpret_cast<ulonglong2*>(&fb);
        }
        __syncwarp();

        unsigned long long acc[8];
        #pragma unroll
        for (int i = 0; i < 8; i++) acc[i] = 0ull;

        #pragma unroll 4
        for (int k = 0; k < 128; k++) {
            float2 w = sW[k * 32 + lane];
            unsigned long long wxx = dup_f32(w.x);
            unsigned long long wyy = dup_f32(w.y);
            ulonglong2 a = sxA[k];
            ulonglong2 b = sxB[k];
            fma2(acc[0], a.x, wxx);
            fma2(acc[1], a.y, wxx);
            fma2(acc[2], a.x, wyy);
            fma2(acc[3], a.y, wyy);
            fma2(acc[4], b.x, wxx);
            fma2(acc[5], b.y, wxx);
            fma2(acc[6], b.x, wyy);
            fma2(acc[7], b.y, wyy);
        }

        #pragma unroll
        for (int h = 0; h < 4; h++) {
            int ia = (h < 2) ? h : h + 2;
            int ib = ia + 2;
            float l0, h0, l1, h1;
            unpack2(acc[ia], l0, h0);
            unpack2(acc[ib], l1, h1);
            emit_row(g_P, row0 + 2 * h,     lane, l0, l1);
            emit_row(g_P, row0 + 2 * h + 1, lane, h0, h1);
        }
        __syncwarp();
    }
}

// ---------------- GEMM2 phase: P2 = (H1[bf16,K=64] @ W2) * dinv, bf16 out ---------
__device__ void phase_gemm2(const float* __restrict__ W, unsigned char* dyn) {
    float2*     sW = (float2*)dyn;                 // 16KB
    ulonglong2* sx = (ulonglong2*)(dyn + 16384);   // 16KB
    const float2* W2 = (const float2*)W;
    for (int t = threadIdx.x; t < 64 * 32; t += 256) sW[t] = W2[t];
    __syncthreads();

    int warp = threadIdx.x >> 5, lane = threadIdx.x & 31;
    ulonglong2* sxA = sx + warp * 128;
    ulonglong2* sxB = sxA + 64;
    const int NG = (N_NODES + 63) >> 6;

    for (int g = blockIdx.x; g < NG; g += gridDim.x) {
        int row0 = g * 64 + warp * 8;
        {
            float2 f[8];
            #pragma unroll
            for (int r = 0; r < 8; r++) {
                int rr = row0 + r; if (rr >= N_NODES) rr = N_NODES - 1;
                f[r] = __bfloat1622float2(g_H1[rr * 32 + lane]);
            }
            float4 a0 = make_float4(f[0].x, f[1].x, f[2].x, f[3].x);
            float4 a1 = make_float4(f[0].y, f[1].y, f[2].y, f[3].y);
            float4 b0 = make_float4(f[4].x, f[5].x, f[6].x, f[7].x);
            float4 b1 = make_float4(f[4].y, f[5].y, f[6].y, f[7].y);
            sxA[2 * lane]     = *reinterpret_cast<ulonglong2*>(&a0);
            sxA[2 * lane + 1] = *reinterpret_cast<ulonglong2*>(&a1);
            sxB[2 * lane]     = *reinterpret_cast<ulonglong2*>(&b0);
            sxB[2 * lane + 1] = *reinterpret_cast<ulonglong2*>(&b1);
        }
        __syncwarp();

        unsigned long long acc[8];
        #pragma unroll
        for (int i = 0; i < 8; i++) acc[i] = 0ull;

        #pragma unroll 4
        for (int k = 0; k < 64; k++) {
            float2 w = sW[k * 32 + lane];
            unsigned long long wxx = dup_f32(w.x);
            unsigned long long wyy = dup_f32(w.y);
            ulonglong2 a = sxA[k];
            ulonglong2 b = sxB[k];
            fma2(acc[0], a.x, wxx);
            fma2(acc[1], a.y, wxx);
            fma2(acc[2], a.x, wyy);
            fma2(acc[3], a.y, wyy);
            fma2(acc[4], b.x, wxx);
            fma2(acc[5], b.y, wxx);
            fma2(acc[6], b.x, wyy);
            fma2(acc[7], b.y, wyy);
        }

        #pragma unroll
        for (int h = 0; h < 4; h++) {
            int ia = (h < 2) ? h : h + 2;
            int ib = ia + 2;
            float l0, h0, l1, h1;
            unpack2(acc[ia], l0, h0);
            unpack2(acc[ib], l1, h1);
            emit_row(g_P2, row0 + 2 * h,     lane, l0, l1);
            emit_row(g_P2, row0 + 2 * h + 1, lane, h0, h1);
        }
        __syncwarp();
    }
}

// ---------------- gather phase (bf16 messages, fp32 accumulate) -------------------
template <int RELU>
__device__ void phase_gather(const __nv_bfloat162* __restrict__ P,
                             __nv_bfloat162* __restrict__ Hout,
                             const float* __restrict__ bias) {
    int lane = threadIdx.x & 31;
    int gwarp = blockIdx.x * 8 + (threadIdx.x >> 5);
    int nwarps = gridDim.x * 8;
    float2 b = reinterpret_cast<const float2*>(bias)[lane];

    for (int n = gwarp; n < N_NODES; n += nwarps) {
        float dn = g_dinv[n];
        int start = g_rowptr[n];
        int end = start + g_deg[n];

        float2 acc = __bfloat1622float2(P[n * 32 + lane]);   // self term

        for (int p = start; p < end; p += 8) {
            int4 sa = *reinterpret_cast<const int4*>(g_csc + p);
            int4 sb = *reinterpret_cast<const int4*>(g_csc + p + 4);
            float2 v0 = __bfloat1622float2(P[(size_t)sa.x * 32 + lane]);
            float2 v1 = __bfloat1622float2(P[(size_t)sa.y * 32 + lane]);
            float2 v2 = __bfloat1622float2(P[(size_t)sa.z * 32 + lane]);
            float2 v3 = __bfloat1622float2(P[(size_t)sa.w * 32 + lane]);
            float2 v4 = __bfloat1622float2(P[(size_t)sb.x * 32 + lane]);
            float2 v5 = __bfloat1622float2(P[(size_t)sb.y * 32 + lane]);
            float2 v6 = __bfloat1622float2(P[(size_t)sb.z * 32 + lane]);
            float2 v7 = __bfloat1622float2(P[(size_t)sb.w * 32 + lane]);
            int rem = end - p;
            acc.x += v0.x; acc.y += v0.y;
            if (rem > 1) { acc.x += v1.x; acc.y += v1.y; }
            if (rem > 2) { acc.x += v2.x; acc.y += v2.y; }
            if (rem > 3) { acc.x += v3.x; acc.y += v3.y; }
            if (rem > 4) { acc.x += v4.x; acc.y += v4.y; }
            if (rem > 5) { acc.x += v5.x; acc.y += v5.y; }
            if (rem > 6) { acc.x += v6.x; acc.y += v6.y; }
            if (rem > 7) { acc.x += v7.x; acc.y += v7.y; }
        }

        float ox = dn * acc.x + b.x;
        float oy = dn * acc.y + b.y;
        if (RELU) { ox = fmaxf(ox, 0.f); oy = fmaxf(oy, 0.f); }
        Hout[n * 32 + lane] = __floats2bfloat162_rn(ox, oy);
    }
}

// ---------------- pool helpers ----------------
__device__ __forceinline__ int lbound(const int* __restrict__ a, int n, int key) {
    int lo = 0, hi = n;
    while (lo < hi) {
        int m = (lo + hi) >> 1;
        if (a[m] < key) lo = m + 1; else hi = m;
    }
    return lo;
}

// ================= THE fused persistent kernel =================
__global__ void __launch_bounds__(256, 3) k_fused(
    const float* __restrict__ x, const int* __restrict__ eidx,
    const int* __restrict__ batch,
    const float* __restrict__ W1, const float* __restrict__ b1,
    const float* __restrict__ W2, const float* __restrict__ b2,
    const float* __restrict__ Wl, const float* __restrict__ bl,
    float* __restrict__ out) {
    extern __shared__ unsigned char dyn[];
    int t = threadIdx.x;
    int gid = blockIdx.x * 256 + t;
    int gstride = gridDim.x * 256;
    const int* dst = eidx + N_EDGES;
    const int4* src4 = (const int4*)eidx;
    const int4* dst4 = (const int4*)dst;

    // ---- P0: zero degree ----
    for (int i = gid; i < N_NODES; i += gstride) g_deg[i] = 0;
    gbar();

    // ---- P1: degree histogram (4 edges/thread) ----
    for (int i = gid; i < N_EDGES / 4; i += gstride) {
        int4 d = dst4[i];
        atomicAdd(&g_deg[d.x], 1);
        atomicAdd(&g_deg[d.y], 1);
        atomicAdd(&g_deg[d.z], 1);
        atomicAdd(&g_deg[d.w], 1);
    }
    gbar();

    // ---- P2: chunk-local scan of padded degrees (+ dinv) ----
    {
        int* smi = (int*)dyn;          // [0..7] warp sums, [8] chunk total
        int lane = t & 31, w = t >> 5;
        for (int c = blockIdx.x; c < NCHUNK; c += gridDim.x) {
            __syncthreads();
            int i = c * 256 + t;
            int v = 0;
            if (i < N_NODES) {
                int d = g_deg[i];
                g_dinv[i] = rsqrtf((float)(d + 1));
                v = (d + 3) & ~3;
            }
            int inc = v;
            #pragma unroll
            for (int o = 1; o < 32; o <<= 1) {
                int u = __shfl_up_sync(0xFFFFFFFFu, inc, o);
                if (lane >= o) inc += u;
            }
            if (lane == 31) smi[w] = inc;
            __syncthreads();
            if (t == 0) {
                int run = 0;
                #pragma unroll
                for (int j = 0; j < 8; j++) { int xx = smi[j]; smi[j] = run; run += xx; }
                g_csum[c] = run;
            }
            __syncthreads();
            if (i < N_NODES) g_rowptr[i] = inc + smi[w] - v;   // exclusive local
        }
    }
    gbar();

    // ---- P3: chunk offsets + cursor init ----
    {
        int* smi = (int*)dyn;
        int lane = t & 31, w = t >> 5;
        for (int c = blockIdx.x; c < NCHUNK; c += gridDim.x) {
            __syncthreads();
            int s = 0;
            for (int j = t; j < c; j += 256) s += g_csum[j];
            #pragma unroll
            for (int o = 16; o; o >>= 1) s += __shfl_down_sync(0xFFFFFFFFu, s, o);
            if (lane == 0) smi[w] = s;
            __syncthreads();
            if (t == 0) {
                int r = 0;
                #pragma unroll
                for (int j = 0; j < 8; j++) r += smi[j];
                smi[9] = r;
            }
            __syncthreads();
            int off = smi[9];
            int i = c * 256 + t;
            if (i < N_NODES) {
                int r = g_rowptr[i] + off;
                g_rowptr[i] = r;
                g_cursor[i] = r;
            }
        }
    }
    gbar();

    // ---- P4 (split): 1/3 blocks fill CSC, 2/3 blocks run GEMM1 ----
    {
        int cscB = gridDim.x / 3;
        if (blockIdx.x < cscB) {
            int id = blockIdx.x * 256 + t;
            int st = cscB * 256;
            for (int i = id; i < N_EDGES / 4; i += st) {
                int4 s = src4[i];
                int4 d = dst4[i];
                g_csc[atomicAdd(&g_cursor[d.x], 1)] = s.x;
                g_csc[atomicAdd(&g_cursor[d.y], 1)] = s.y;
                g_csc[atomicAdd(&g_cursor[d.z], 1)] = s.z;
                g_csc[atomicAdd(&g_cursor[d.w], 1)] = s.w;
            }
        } else {
            phase_gemm1(x, W1, dyn, blockIdx.x - cscB, gridDim.x - cscB);
        }
    }
    gbar();

    // ---- P5: gather layer 1 (relu) ----
    phase_gather<1>(g_P, g_H1, b1);
    gbar();

    // ---- P6: GEMM2 ----
    phase_gemm2(W2, dyn);
    gbar();

    // ---- P7: gather layer 2 ----
    phase_gather<0>(g_P2, g_H2, b2);
    gbar();

    // ---- P8: mean pool per graph + linear head ----
    {
        float2* sm = (float2*)dyn;
        int cp   = t & 31;
        int part = t >> 5;
        for (int g = blockIdx.x; g < N_GRAPHS; g += gridDim.x) {
            __syncthreads();
            int lo = lbound(batch, N_NODES, g);
            int hi = lbound(batch, N_NODES, g + 1);
            float2 s = make_float2(0.f, 0.f);
            for (int n = lo + part; n < hi; n += 8) {
                float2 v = __bfloat1622float2(g_H2[(size_t)n * 32 + cp]);
                s.x += v.x; s.y += v.y;
            }
            sm[t] = s;
            __syncthreads();
            if (t < 32) {
                float2 v = sm[t];
                #pragma unroll
                for (int p = 1; p < 8; p++) {
                    float2 u = sm[t + 32 * p];
                    v.x += u.x; v.y += u.y;
                }
                int cnt = hi - lo;
                float inv = 1.f / (float)(cnt > 0 ? cnt : 1);
                float2 w = reinterpret_cast<const float2*>(Wl)[t];
                sm[t] = make_float2(v.x * inv * w.x + v.y * inv * w.y, 0.f);
            }
            __syncthreads();
            if (t == 0) {
                float r = 0.f;
                #pragma unroll
                for (int c = 0; c < 32; c++) r += sm[c].x;
                out[g] = r + bl[0];
            }
        }
    }
}

// ---------------- launch: ONE kernel ----------------
extern "C" void kernel_launch(void* const* d_in, const int* in_sizes, int n_in,
                              void* d_out, int out_size) {
    const float* x     = (const float*)d_in[0];
    const int*   eidx  = (const int*)d_in[1];
    const int*   batch = (const int*)d_in[2];
    const float* W1    = (const float*)d_in[3];
    const float* b1    = (const float*)d_in[4];
    const float* W2    = (const float*)d_in[5];
    const float* b2    = (const float*)d_in[6];
    const float* Wl    = (const float*)d_in[7];
    const float* bl    = (const float*)d_in[8];
    float* out = (float*)d_out;

    cudaFuncSetAttribute(k_fused, cudaFuncAttributeMaxDynamicSharedMemorySize, 65536);

    int dev = 0, sms = 148;
    cudaGetDevice(&dev);
    cudaDeviceGetAttribute(&sms, cudaDevAttrMultiProcessorCount, dev);
    int grid = sms * 3;   // exactly resident: 3 blocks/SM via __launch_bounds__ + 64KB smem

    k_fused<<<grid, 256, 65536>>>(x, eidx, batch, W1, b1, W2, b2, Wl, bl, out);
}